// round 17
// baseline (speedup 1.0000x reference)
#include <cuda_runtime.h>
#include <cuda_bf16.h>
#include <math.h>

#define N_ROWS 8192
#define D_DIM  128
#define STAT_VB 1024          // stats units (8 rows each)
#define NT_SIDE 32            // 8192 / 256
#define NTILES  528           // triangle: 32*33/2
#define GRID 592              // 148 SMs x 4 resident: single wave
#define PB 24                 // smem pitch in bf16 (48B): conflict-free frags
#define SQ2 1.41421356237f
#define THRESH 2.0f

// ---------------- device scratch ----------------
__device__ float   d_vsum[2][D_DIM];
__device__ float4  d_part[STAT_VB];     // {focal, graph, sn0, sn1}
__device__ float   d_pc[STAT_VB];       // count of label-1 rows
__device__ double  d_cross;             // ordered cross-pair margin sum
__device__ unsigned d_done;

__device__ __forceinline__ float warp_sum(float v) {
    #pragma unroll
    for (int o = 16; o > 0; o >>= 1) v += __shfl_xor_sync(0xffffffffu, v, o);
    return v;
}
__device__ __forceinline__ double warp_sum_d(double v) {
    #pragma unroll
    for (int o = 16; o > 0; o >>= 1) v += __shfl_xor_sync(0xffffffffu, v, o);
    return v;
}

// exact fp32 recheck on ORIGINAL rows; norms computed inline
__device__ __noinline__ float rare_pair(const float* __restrict__ feat,
                                        const float* __restrict__ tgt,
                                        int gi, int gj) {
    if (gi == gj) return 0.0f;
    float ti = tgt[gi], tj = tgt[gj];
    if ((ti > 0.5f) == (tj > 0.5f)) return 0.0f;
    const float* A = feat + (size_t)gi * D_DIM;
    const float* B = feat + (size_t)gj * D_DIM;
    float dot = 0.0f, na = 0.0f, nb = 0.0f;
    #pragma unroll 4
    for (int d = 0; d < D_DIM; ++d) {
        float a = A[d], b = B[d];
        dot += a * b; na += a * a; nb += b * b;
    }
    float sq = fmaxf(na + nb - 2.0f * dot, 0.0f);
    float t = 1.0f - sqrtf(sq);
    return (t > 0.0f) ? t * t : 0.0f;
}

// build one bf16 screen row (12 feat dims + norm-aux + label-aux = 16)
__device__ __forceinline__ void make_row(const float* __restrict__ F,
                                         float lab, float sgn, int sideB,
                                         __nv_bfloat16* dst) {
    float4 x0 = *(const float4*)(F);
    float4 x1 = *(const float4*)(F + 4);
    float4 x2 = *(const float4*)(F + 8);
    float nsq12 = x0.x*x0.x + x0.y*x0.y + x0.z*x0.z + x0.w*x0.w
                + x1.x*x1.x + x1.y*x1.y + x1.z*x1.z + x1.w*x1.w
                + x2.x*x2.x + x2.y*x2.y + x2.z*x2.z + x2.w*x2.w;
    __nv_bfloat162 p0 = __floats2bfloat162_rn(sgn*x0.x, sgn*x0.y);
    __nv_bfloat162 p1 = __floats2bfloat162_rn(sgn*x0.z, sgn*x0.w);
    __nv_bfloat162 p2 = __floats2bfloat162_rn(sgn*x1.x, sgn*x1.y);
    __nv_bfloat162 p3 = __floats2bfloat162_rn(sgn*x1.z, sgn*x1.w);
    __nv_bfloat162 p4 = __floats2bfloat162_rn(sgn*x2.x, sgn*x2.y);
    __nv_bfloat162 p5 = __floats2bfloat162_rn(sgn*x2.z, sgn*x2.w);
    __nv_bfloat162 p6 = sideB ? __floats2bfloat162_rn(1.0f, nsq12)
                              : __floats2bfloat162_rn(nsq12, 1.0f);
    __nv_bfloat162 p7 = (lab > 0.5f) ? __floats2bfloat162_rn(0.0f, 16.0f)
                                     : __floats2bfloat162_rn(16.0f, 0.0f);
    uint4 lo, hi;
    lo.x = *(unsigned*)&p0; lo.y = *(unsigned*)&p1;
    lo.z = *(unsigned*)&p2; lo.w = *(unsigned*)&p3;
    hi.x = *(unsigned*)&p4; hi.y = *(unsigned*)&p5;
    hi.z = *(unsigned*)&p6; hi.w = *(unsigned*)&p7;
    *(uint4*)(dst)     = lo;
    *(uint4*)(dst + 8) = hi;
}

// ---------------- single wave, balanced tile+stats per block ----------------
__global__ void __launch_bounds__(256, 4) fused_kernel(
    const float* __restrict__ preds,
    const float* __restrict__ targets,
    const float* __restrict__ features,
    const float* __restrict__ gfeat,
    float* __restrict__ out)
{
    __shared__ __nv_bfloat16 sA[256 * PB];
    __shared__ __nv_bfloat16 sB[256 * PB];
    __shared__ float s_v[8][D_DIM];
    __shared__ float s_g[8][D_DIM];
    __shared__ float s_sn[2];
    __shared__ float s_focal, s_graph;
    __shared__ int   s_lab[8];
    __shared__ float redw[8];
    __shared__ double sd[5][8];
    __shared__ double sred[256];
    __shared__ unsigned s_ticket;

    int tid = threadIdx.x;
    int bid = blockIdx.x;
    int warp = tid >> 5, lane = tid & 31;

    bool has_tile = (bid < NTILES);
    int  nvb = (bid < 432) ? 2 : 1;        // vbs: bid, and bid+592 if bid<432

    int row0 = 0, col0 = 0;
    float wgt = 1.0f;

    // ============ tile prologue: LDG burst -> bf16 rows in smem =============
    if (has_tile) {
        int k = bid;
        int tr = (int)((65.0f - sqrtf(65.0f * 65.0f - 8.0f * (float)k)) * 0.5f);
        if (tr > NT_SIDE - 1) tr = NT_SIDE - 1;
        if (tr < 0) tr = 0;
        while (tr < NT_SIDE - 1 && (tr + 1) * (65 - (tr + 1)) / 2 <= k) ++tr;
        while (tr > 0 && tr * (65 - tr) / 2 > k) --tr;
        int tc = tr + (k - tr * (65 - tr) / 2);
        row0 = tr * 256; col0 = tc * 256;
        wgt = (tr == tc) ? 1.0f : 2.0f;

        int ga = row0 + tid, gb = col0 + tid;
        make_row(features + (size_t)ga * D_DIM, targets[ga], -SQ2, 0, sA + tid * PB);
        make_row(features + (size_t)gb * D_DIM, targets[gb],  SQ2, 1, sB + tid * PB);
        // no sync yet: stats phase below has its own syncs, which order these
        // stores before the MMA phase for all threads.
    }

    // ============ stats: 1-2 virtual blocks (proven R15/R16 body) ============
    for (int it = 0; it < nvb; ++it) {
        int vb = (it == 0) ? bid : bid + GRID;

        if (tid == 254) { s_sn[0] = 0.0f; s_sn[1] = 0.0f; }
        if (tid == 255) { s_focal = 0.0f; s_graph = 0.0f; }

        int i = vb * 8 + warp;

        float4 f = *(const float4*)(features + (size_t)i * D_DIM + lane * 4);
        float c  = f.x*f.x + f.y*f.y + f.z*f.z + f.w*f.w;
        float nsq = warp_sum(c);

        float4 ga4 = *(const float4*)(gfeat + (size_t)i * D_DIM + lane * 4);

        float tgt = targets[i];
        int lab = (tgt > 0.5f) ? 1 : 0;
        if (lane == 0) s_lab[warp] = lab;

        s_v[warp][lane * 4 + 0] = f.x;
        s_v[warp][lane * 4 + 1] = f.y;
        s_v[warp][lane * 4 + 2] = f.z;
        s_v[warp][lane * 4 + 3] = f.w;
        *(float4*)&s_g[warp][lane * 4] = ga4;
        __syncthreads();   // init + stores visible before atomics/reads

        if (lane == 0) atomicAdd(&s_sn[lab], nsq);
        if (lane == 0) {
            float p = preds[i];
            float bce = fmaxf(p, 0.0f) - p * tgt + log1pf(expf(-fabsf(p)));
            float pt = expf(-bce);
            float om = 1.0f - pt;
            atomicAdd(&s_focal, 0.25f * om * om * bce);
        }

        if (i >= 1) {
            float4 gb4;
            if (warp == 0)
                gb4 = *(const float4*)(gfeat + (size_t)(i - 1) * D_DIM + lane * 4);
            else
                gb4 = *(const float4*)&s_g[warp - 1][lane * 4];
            float dx = ga4.x - gb4.x, dy = ga4.y - gb4.y;
            float dz = ga4.z - gb4.z, dw = ga4.w - gb4.w;
            float ds = warp_sum(dx*dx + dy*dy + dz*dz + dw*dw);
            if (lane == 0) atomicAdd(&s_graph, sqrtf(ds));
        }

        {
            int cls = tid >> 7, comp = tid & 127;
            float sum = 0.0f;
            #pragma unroll
            for (int w = 0; w < 8; ++w)
                if (s_lab[w] == cls) sum += s_v[w][comp];
            if (sum != 0.0f) atomicAdd(&d_vsum[cls][comp], sum);
        }
        __syncthreads();   // shared atomics complete before leader reads
        if (tid == 0) {
            int c1 = 0;
            #pragma unroll
            for (int w = 0; w < 8; ++w) c1 += s_lab[w];
            d_part[vb] = make_float4(s_focal, s_graph, s_sn[0], s_sn[1]);
            d_pc[vb] = (float)c1;
        }
        __syncthreads();   // leader done before next-iter re-init
    }

    // ============ tile screen (smem rows long since written) ============
    float lsum = 0.0f;
    if (has_tile) {
        __syncthreads();   // cross-warp visibility of sA/sB (cheap safety)

        int g = lane >> 2, t = lane & 3;
        int r0 = warp * 32;

        unsigned a[2][4];
        #pragma unroll
        for (int rb = 0; rb < 2; ++rb) {
            const __nv_bfloat16* base = sA + (r0 + rb * 16 + g) * PB + t * 2;
            a[rb][0] = *(const unsigned*)(base);
            a[rb][1] = *(const unsigned*)(base + 8 * PB);
            a[rb][2] = *(const unsigned*)(base + 8);
            a[rb][3] = *(const unsigned*)(base + 8 * PB + 8);
        }

        unsigned long long fmask = 0ull;
        #pragma unroll 8
        for (int cb = 0; cb < 32; ++cb) {
            const __nv_bfloat16* bb = sB + (cb * 8 + g) * PB + t * 2;
            unsigned b0 = *(const unsigned*)(bb);
            unsigned b1 = *(const unsigned*)(bb + 8);
            #pragma unroll
            for (int rb = 0; rb < 2; ++rb) {
                float d0, d1, d2, d3;
                asm("mma.sync.aligned.m16n8k16.row.col.f32.bf16.bf16.f32 "
                    "{%0,%1,%2,%3},{%4,%5,%6,%7},{%8,%9},{%10,%10,%10,%10};"
                    : "=f"(d0), "=f"(d1), "=f"(d2), "=f"(d3)
                    : "r"(a[rb][0]), "r"(a[rb][1]), "r"(a[rb][2]), "r"(a[rb][3]),
                      "r"(b0), "r"(b1), "f"(0.0f));
                float mn = fminf(fminf(d0, d1), fminf(d2, d3));
                if (mn < THRESH) fmask |= 1ull << (cb * 2 + rb);
            }
        }

        if (fmask) {   // ~100 quads chip-wide survive the 12-dim+label screen
            #pragma unroll 1
            while (fmask) {
                int b = __ffsll((long long)fmask) - 1;
                fmask &= fmask - 1;
                int cb = b >> 1, rb = b & 1;
                int gib = row0 + r0 + rb * 16 + g;
                int gjb = col0 + cb * 8 + t * 2;
                #pragma unroll 1
                for (int q = 0; q < 4; ++q) {
                    int gi = gib + (q >> 1) * 8;
                    int gj = gjb + (q & 1);
                    lsum += wgt * rare_pair(features, targets, gi, gj);
                }
            }
        }
    }

    // ============ common: reduce + ticket finalize ============
    lsum = warp_sum(lsum);
    if (lane == 0) redw[warp] = lsum;
    __syncthreads();
    if (tid == 0) {
        float s = 0.0f;
        #pragma unroll
        for (int w = 0; w < 8; ++w) s += redw[w];
        if (s != 0.0f) atomicAdd(&d_cross, (double)s);
        __threadfence();
        s_ticket = atomicAdd(&d_done, 1u);
    }
    __syncthreads();

    if (s_ticket == GRID - 1) {
        if (tid == 0) __threadfence();
        __syncthreads();

        double pf = 0.0, pg = 0.0, p0 = 0.0, p1 = 0.0, pc = 0.0;
        #pragma unroll
        for (int kk = 0; kk < STAT_VB / 256; ++kk) {
            float4 p = d_part[tid + kk * 256];
            pf += p.x; pg += p.y; p0 += p.z; p1 += p.w;
            pc += d_pc[tid + kk * 256];
        }
        pf = warp_sum_d(pf); pg = warp_sum_d(pg);
        p0 = warp_sum_d(p0); p1 = warp_sum_d(p1);
        pc = warp_sum_d(pc);
        if (lane == 0) {
            sd[0][warp] = pf; sd[1][warp] = pg;
            sd[2][warp] = p0; sd[3][warp] = p1;
            sd[4][warp] = pc;
        }

        int cls = tid >> 7, comp = tid & 127;
        double v = (double)d_vsum[cls][comp];
        sred[tid] = v * v;
        __syncthreads();
        for (int st = 64; st > 0; st >>= 1) {
            if (comp < st) sred[tid] += sred[tid + st];
            __syncthreads();
        }
        if (tid == 0) {
            double focal_s = 0.0, graph_s = 0.0, sn0 = 0.0, sn1 = 0.0, c1 = 0.0;
            #pragma unroll
            for (int w = 0; w < 8; ++w) {
                focal_s += sd[0][w]; graph_s += sd[1][w];
                sn0 += sd[2][w]; sn1 += sd[3][w];
                c1 += sd[4][w];
            }
            double vn0 = sred[0], vn1 = sred[128];
            double dn1 = c1, dn0 = (double)N_ROWS - c1;
            double same = 2.0 * (dn0 * sn0 - vn0) + 2.0 * (dn1 * sn1 - vn1);
            double NN = (double)N_ROWS * (double)N_ROWS;
            double contrast = (same + d_cross) / NN;
            double focal = focal_s / (double)N_ROWS;
            double graph = 0.1 * graph_s / (double)(N_ROWS - 1);
            out[0] = (float)(focal + contrast + graph);
            d_cross = 0.0;
            d_done  = 0u;
        }
        d_vsum[cls][comp] = 0.0f;
    }
}

// ---------------- launch ----------------
extern "C" void kernel_launch(void* const* d_in, const int* in_sizes, int n_in,
                              void* d_out, int out_size) {
    const float* preds    = (const float*)d_in[0];
    const float* targets  = (const float*)d_in[1];
    const float* features = (const float*)d_in[2];
    const float* gfeat    = (const float*)d_in[3];
    float* out = (float*)d_out;

    fused_kernel<<<GRID, 256>>>(preds, targets, features, gfeat, out);
}